// round 3
// baseline (speedup 1.0000x reference)
#include <cuda_runtime.h>

// Problem constants (fixed by dataset)
#define D_MODEL 1024
#define ADAPT   128
#define NUM_LIB 8
#define NPAIR   (NUM_LIB * NUM_LIB)   // 64
#define MAXB    1024
#define KC      4                      // K-split for gemm1
#define KCH     (D_MODEL / KC)         // 256
#define RT      16                     // row tile
#define PAD     20                     // smem row pad (4-float aligned, conflict-lite)

typedef unsigned long long ull;

// Packed fp32x2 FMA (sm_10x): d = a*b + c per 32-bit lane
#define FMA2(d, a, b, c) \
    asm("fma.rn.f32x2 %0, %1, %2, %3;" : "=l"(d) : "l"(a), "l"(b), "l"(c))
#define PACK2(d, s) \
    asm("mov.b64 %0, {%1, %1};" : "=l"(d) : "f"(s))
#define UNPACK2(lo, hi, s) \
    asm("mov.b64 {%0, %1}, %2;" : "=f"(lo), "=f"(hi) : "l"(s))

// Device scratch (no allocations allowed)
__device__ int   g_off[NPAIR + 1];
__device__ int   g_rows[MAXB];
__device__ float g_hp[KC][MAXB * ADAPT];   // partial pre-activation sums

// ---------------------------------------------------------------------------
// Build per-pair CSR of row indices. One CTA, 1024 threads.
// ---------------------------------------------------------------------------
__global__ void k_build(const int* __restrict__ src, const int* __restrict__ tgt, int B) {
    __shared__ int cnt[NPAIR];
    __shared__ int off[NPAIR + 1];
    int t = threadIdx.x;
    if (t < NPAIR) cnt[t] = 0;
    __syncthreads();
    int p = -1, slot = 0;
    if (t < B) {
        int s = src[t], g = tgt[t];
        if (s != g) {
            p = s * NUM_LIB + g;
            slot = atomicAdd(&cnt[p], 1);
        }
    }
    __syncthreads();
    if (t == 0) {
        int acc = 0;
        for (int i = 0; i < NPAIR; i++) { off[i] = acc; acc += cnt[i]; }
        off[NPAIR] = acc;
    }
    __syncthreads();
    if (t <= NPAIR) g_off[t] = off[t];
    if (p >= 0) g_rows[off[p] + slot] = t;
}

// ---------------------------------------------------------------------------
// Identity rows: out[b] = x[b]. Grid-stride over rows, 128 CTAs x 256 thr.
// ---------------------------------------------------------------------------
__global__ void __launch_bounds__(256)
k_copy(const float* __restrict__ x,
       const int* __restrict__ src, const int* __restrict__ tgt,
       float* __restrict__ out, int B) {
    for (int b = blockIdx.x; b < B; b += gridDim.x) {
        if (src[b] != tgt[b]) continue;
        const float4* xi = (const float4*)(x + (size_t)b * D_MODEL);
        float4* yo = (float4*)(out + (size_t)b * D_MODEL);
        yo[threadIdx.x] = xi[threadIdx.x];   // 256 float4 = 1024 floats
    }
}

// ---------------------------------------------------------------------------
// GEMM1 (K-split): g_hp[kz][row, a] = x[row, kz*256:+256] . W1[p, slice, a]
// grid (NPAIR, KC, 2), 256 thr. Thread: a = t&127, row-half rh = t>>7 (8 rows).
// x staged TRANSPOSED in smem [k][row] (pad 20); rows packed in f32x2 lanes.
// ---------------------------------------------------------------------------
__global__ void __launch_bounds__(256, 4)
k_gemm1(const float* __restrict__ x, const float* __restrict__ W1) {
    __shared__ __align__(16) float xs[KCH * PAD];   // 20 KB
    int p  = blockIdx.x;
    int kz = blockIdx.y;
    int begin = g_off[p], end = g_off[p + 1];
    int t  = threadIdx.x;
    int a  = t & 127;
    int rh = t >> 7;
    const float* Wp = W1 + ((size_t)p * D_MODEL + (size_t)kz * KCH) * ADAPT + a;
    float* hp = g_hp[kz];

    for (int base = begin + blockIdx.z * RT; base < end; base += 2 * RT) {
        int n = min(RT, end - base);
        __syncthreads();                 // previous tile done with xs
        // stage x rows transposed: xs[k][r], zero-pad missing rows
        for (int i = t; i < RT * KCH; i += 256) {
            int r = i >> 8;              // KCH = 256
            int k = i & 255;
            float v = 0.f;
            if (r < n)
                v = x[(size_t)g_rows[base + r] * D_MODEL + kz * KCH + k];
            xs[k * PAD + r] = v;
        }
        __syncthreads();

        ull acc0 = 0, acc1 = 0, acc2 = 0, acc3 = 0;   // rows rh*8 + {0..7} as 4 pairs
        #pragma unroll 2
        for (int k = 0; k < KCH; k += 4) {
            float w0 = Wp[(size_t)(k + 0) * ADAPT];
            float w1 = Wp[(size_t)(k + 1) * ADAPT];
            float w2 = Wp[(size_t)(k + 2) * ADAPT];
            float w3 = Wp[(size_t)(k + 3) * ADAPT];
            ull W0, W1r, W2r, W3r;
            PACK2(W0, w0); PACK2(W1r, w1); PACK2(W2r, w2); PACK2(W3r, w3);
            const float* xb = xs + rh * 8;
            {   ulonglong2 v0 = *(const ulonglong2*)(xb + (k + 0) * PAD);
                ulonglong2 v1 = *(const ulonglong2*)(xb + (k + 0) * PAD + 4);
                FMA2(acc0, v0.x, W0, acc0); FMA2(acc1, v0.y, W0, acc1);
                FMA2(acc2, v1.x, W0, acc2); FMA2(acc3, v1.y, W0, acc3); }
            {   ulonglong2 v0 = *(const ulonglong2*)(xb + (k + 1) * PAD);
                ulonglong2 v1 = *(const ulonglong2*)(xb + (k + 1) * PAD + 4);
                FMA2(acc0, v0.x, W1r, acc0); FMA2(acc1, v0.y, W1r, acc1);
                FMA2(acc2, v1.x, W1r, acc2); FMA2(acc3, v1.y, W1r, acc3); }
            {   ulonglong2 v0 = *(const ulonglong2*)(xb + (k + 2) * PAD);
                ulonglong2 v1 = *(const ulonglong2*)(xb + (k + 2) * PAD + 4);
                FMA2(acc0, v0.x, W2r, acc0); FMA2(acc1, v0.y, W2r, acc1);
                FMA2(acc2, v1.x, W2r, acc2); FMA2(acc3, v1.y, W2r, acc3); }
            {   ulonglong2 v0 = *(const ulonglong2*)(xb + (k + 3) * PAD);
                ulonglong2 v1 = *(const ulonglong2*)(xb + (k + 3) * PAD + 4);
                FMA2(acc0, v0.x, W3r, acc0); FMA2(acc1, v0.y, W3r, acc1);
                FMA2(acc2, v1.x, W3r, acc2); FMA2(acc3, v1.y, W3r, acc3); }
        }
        ull accs[4] = {acc0, acc1, acc2, acc3};
        #pragma unroll
        for (int j = 0; j < 4; j++) {
            float lo, hi;
            UNPACK2(lo, hi, accs[j]);
            int r0 = rh * 8 + 2 * j;
            if (r0 < n)     hp[(size_t)g_rows[base + r0]     * ADAPT + a] = lo;
            if (r0 + 1 < n) hp[(size_t)g_rows[base + r0 + 1] * ADAPT + a] = hi;
        }
    }
}

// ---------------------------------------------------------------------------
// GEMM2: out[row, d] = relu(sum_kz g_hp + b1) . W2[p,:,d] + b2[p,d]
// grid (NPAIR, 8, 2), 256 thr. Thread: d = dc*128 + (t&127), rh = t>>7.
// h staged TRANSPOSED in smem [a][row] (pad 20); rows packed in f32x2 lanes.
// ---------------------------------------------------------------------------
__global__ void __launch_bounds__(256, 4)
k_gemm2(const float* __restrict__ W2, const float* __restrict__ b1,
        const float* __restrict__ b2, float* __restrict__ out) {
    __shared__ __align__(16) float hs[ADAPT * PAD];   // 10 KB
    int p  = blockIdx.x;
    int dc = blockIdx.y;
    int begin = g_off[p], end = g_off[p + 1];
    int t  = threadIdx.x;
    int a  = t & 127;
    int rh = t >> 7;
    int d  = dc * 128 + a;
    const float* Wp = W2 + (size_t)p * ADAPT * D_MODEL + d;
    float bb2 = b2[(size_t)p * D_MODEL + d];

    for (int base = begin + blockIdx.z * RT; base < end; base += 2 * RT) {
        int n = min(RT, end - base);
        __syncthreads();                 // previous tile done with hs
        // stage h = relu(sum of K-partials + b1), transposed [a][r], zero-pad
        for (int i = t; i < RT * ADAPT; i += 256) {
            int r  = i >> 7;
            int aa = i & 127;
            float v = 0.f;
            if (r < n) {
                size_t idx = (size_t)g_rows[base + r] * ADAPT + aa;
                v = fmaxf(g_hp[0][idx] + g_hp[1][idx] +
                          g_hp[2][idx] + g_hp[3][idx] + b1[p * ADAPT + aa], 0.f);
            }
            hs[aa * PAD + r] = v;
        }
        __syncthreads();

        ull acc0 = 0, acc1 = 0, acc2 = 0, acc3 = 0;
        #pragma unroll 2
        for (int aa = 0; aa < ADAPT; aa += 4) {
            float w0 = Wp[(size_t)(aa + 0) * D_MODEL];
            float w1 = Wp[(size_t)(aa + 1) * D_MODEL];
            float w2 = Wp[(size_t)(aa + 2) * D_MODEL];
            float w3 = Wp[(size_t)(aa + 3) * D_MODEL];
            ull W0, W1r, W2r, W3r;
            PACK2(W0, w0); PACK2(W1r, w1); PACK2(W2r, w2); PACK2(W3r, w3);
            const float* hb = hs + rh * 8;
            {   ulonglong2 v0 = *(const ulonglong2*)(hb + (aa + 0) * PAD);
                ulonglong2 v1 = *(const ulonglong2*)(hb + (aa + 0) * PAD + 4);
                FMA2(acc0, v0.x, W0, acc0); FMA2(acc1, v0.y, W0, acc1);
                FMA2(acc2, v1.x, W0, acc2); FMA2(acc3, v1.y, W0, acc3); }
            {   ulonglong2 v0 = *(const ulonglong2*)(hb + (aa + 1) * PAD);
                ulonglong2 v1 = *(const ulonglong2*)(hb + (aa + 1) * PAD + 4);
                FMA2(acc0, v0.x, W1r, acc0); FMA2(acc1, v0.y, W1r, acc1);
                FMA2(acc2, v1.x, W1r, acc2); FMA2(acc3, v1.y, W1r, acc3); }
            {   ulonglong2 v0 = *(const ulonglong2*)(hb + (aa + 2) * PAD);
                ulonglong2 v1 = *(const ulonglong2*)(hb + (aa + 2) * PAD + 4);
                FMA2(acc0, v0.x, W2r, acc0); FMA2(acc1, v0.y, W2r, acc1);
                FMA2(acc2, v1.x, W2r, acc2); FMA2(acc3, v1.y, W2r, acc3); }
            {   ulonglong2 v0 = *(const ulonglong2*)(hb + (aa + 3) * PAD);
                ulonglong2 v1 = *(const ulonglong2*)(hb + (aa + 3) * PAD + 4);
                FMA2(acc0, v0.x, W3r, acc0); FMA2(acc1, v0.y, W3r, acc1);
                FMA2(acc2, v1.x, W3r, acc2); FMA2(acc3, v1.y, W3r, acc3); }
        }
        ull accs[4] = {acc0, acc1, acc2, acc3};
        #pragma unroll
        for (int j = 0; j < 4; j++) {
            float lo, hi;
            UNPACK2(lo, hi, accs[j]);
            int r0 = rh * 8 + 2 * j;
            if (r0 < n)     out[(size_t)g_rows[base + r0]     * D_MODEL + d] = lo + bb2;
            if (r0 + 1 < n) out[(size_t)g_rows[base + r0 + 1] * D_MODEL + d] = hi + bb2;
        }
    }
}

// ---------------------------------------------------------------------------
extern "C" void kernel_launch(void* const* d_in, const int* in_sizes, int n_in,
                              void* d_out, int out_size) {
    const float* x   = (const float*)d_in[0];
    const int*   src = (const int*)d_in[1];
    const int*   tgt = (const int*)d_in[2];
    const float* W1  = (const float*)d_in[3];
    const float* b1  = (const float*)d_in[4];
    const float* W2  = (const float*)d_in[5];
    const float* b2  = (const float*)d_in[6];
    float* out = (float*)d_out;
    int B = in_sizes[1];  // 1024

    k_build<<<1, 1024>>>(src, tgt, B);
    k_copy<<<128, 256>>>(x, src, tgt, out, B);
    k_gemm1<<<dim3(NPAIR, KC, 2), 256>>>(x, W1);
    k_gemm2<<<dim3(NPAIR, 8, 2), 256>>>(W2, b1, b2, out);
}